// round 9
// baseline (speedup 1.0000x reference)
#include <cuda_runtime.h>
#include <math.h>

// Problem constants
#define BQ 4
#define NQ 23
#define NPAIR 15
#define RLQ 32
#define FEAT 1121          // 1 + 5*32 + 15*64
#define NW 23              // one warp per j-atom
#define NT (NW * 32)       // 736 threads

// 0.5*cos(theta_l), 0.5*sin(theta_l), theta_l = pi*l/7
__constant__ float CTH2[8] = {
     0.5f,            0.45048443395f,  0.31174490093f,  0.11126046698f,
    -0.11126046698f, -0.31174490093f, -0.45048443395f, -0.5f };
__constant__ float STH2[8] = {
     0.0f,            0.21694186956f,  0.39091574124f,  0.48746395609f,
     0.48746395609f,  0.39091574124f,  0.21694186956f,  0.0f };
// pair p -> (ta, tb), ta<=tb
__constant__ int PA[NPAIR] = {0,0,0,0,0,1,1,1,1,2,2,2,3,3,4};
__constant__ int PB[NPAIR] = {0,1,2,3,4,1,2,3,4,2,3,4,3,4,4};

__global__ __launch_bounds__(NT, 1)
void ani_kernel(const float* __restrict__ coords,
                const int*   __restrict__ anum,
                float*       __restrict__ out)
{
    __shared__ float    wacc[NW][5 * 64];   // per-warp angular partials
    __shared__ float    radp[NW][RLQ];      // per-warp radial partials
    __shared__ float4   pairbuf[NW][NQ];    // type-compacted (ct,st,ravg,fp)
    __shared__ unsigned s_amask[5];         // typ==t && fac>0
    __shared__ unsigned s_rmask[5];         // typ==t

    const int bi = blockIdx.x;
    const int b  = bi / NQ;
    const int i  = bi % NQ;
    const int tid  = threadIdx.x;
    const int w    = tid >> 5;
    const int lane = tid & 31;
    const unsigned FULL = 0xFFFFFFFFu;

    // ---- per-warp redundant prologue (L1-broadcast loads, no block sync) ----
    const bool v = lane < NQ;
    float x = 0.f, y = 0.f, z = 0.f;
    int   t = -1;
    if (v) {
        const float BOHR = 0.52917721092f;
        x = coords[(b * NQ + lane) * 3 + 0] * BOHR;
        y = coords[(b * NQ + lane) * 3 + 1] * BOHR;
        z = coords[(b * NQ + lane) * 3 + 2] * BOHR;
        int zz = anum[b * NQ + lane];
        t = (zz == 1) ? 0 : (zz == 6) ? 1 : (zz == 7) ? 2 :
            (zz == 8) ? 3 : (zz == 16) ? 4 : -1;
    }
    const float xi = __shfl_sync(FULL, x, i);
    const float yi = __shfl_sync(FULL, y, i);
    const float zi = __shfl_sync(FULL, z, i);

    const float dx = x - xi, dy = y - yi, dz = z - zi;
    const float dr = sqrtf(dx * dx + dy * dy + dz * dz + 1e-7f);
    const bool  ne = v && (lane != i);
    const float fr = (ne && dr < 4.6f) ? 0.5f * (__cosf(0.68294733639181f * dr) + 1.0f) : 0.0f;
    const float fa = (ne && dr < 3.1f) ? 0.5f * (__cosf(1.01341709287626f * dr) + 1.0f) : 0.0f;

    unsigned am[5], rm[5];
    #pragma unroll
    for (int tt = 0; tt < 5; tt++) {
        am[tt] = __ballot_sync(FULL, (t == tt) && (fa > 0.0f));
        rm[tt] = __ballot_sync(FULL, (t == tt));
    }
    if (tid == 0) {
        #pragma unroll
        for (int tt = 0; tt < 5; tt++) { s_amask[tt] = am[tt]; s_rmask[tt] = rm[tt]; }
    }

    // type-group offsets (warp-uniform)
    int off[5];
    off[0] = 0;
    #pragma unroll
    for (int tt = 1; tt < 5; tt++) off[tt] = off[tt - 1] + __popc(am[tt - 1]);

    // j = w per-warp broadcast values
    const int   tj  = __shfl_sync(FULL, t,  w);
    const float fj  = __shfl_sync(FULL, fa, w);
    const float fjr = __shfl_sync(FULL, fr, w);
    const float djx = __shfl_sync(FULL, dx, w);
    const float djy = __shfl_sync(FULL, dy, w);
    const float djz = __shfl_sync(FULL, dz, w);
    const float djd = __shfl_sync(FULL, dr, w);

    // ---- radial partial: warp w, one shell per lane ----
    {
        const float step = 4.6f / 31.0f;
        const float nita = -3.0f / (step * step);
        float rv = 0.0f;
        if (tj >= 0 && fjr > 0.0f) {
            float dd = djd - step * (float)lane;
            rv = __expf(nita * dd * dd) * fjr;
        }
        radp[w][lane] = rv;
    }

    // ---- phase A: lane k computes pair (j=w, k=lane) scalars, compacts by type ----
    {
        float vm = djx * dx + djy * dy + djz * dz;
        float ct = __fdividef(vm, fmaf(djd, dr, 1e-5f));
        float x2 = fmaxf(1.0f - ct * ct, 0.0f);
        float st = x2 * rsqrtf(fmaxf(x2, 1e-12f));   // sin(arccos(ct))
        float rv = fmaf(dr, 0.5f, 0.5f * djd);       // (d_j + d_k)/2
        float fp = 2.0f * fj * fa;                   // 2 f_j f_k

        if (t >= 0 && fa > 0.0f) {
            int rank = __popc(am[t] & ((1u << lane) - 1u));
            pairbuf[w][off[t] + rank] = make_float4(ct, st, rv, fp);
        }
    }
    __syncwarp();

    // ---- phase B: dense counted loops per type group (pipelineable) ----
    float acc[10] = {0.f,0.f,0.f,0.f,0.f,0.f,0.f,0.f,0.f,0.f};
    if (tj >= 0 && fj > 0.0f) {
        const int   thi  = lane & 7;
        const int   rsi  = lane >> 3;
        const float cth2 = CTH2[thi];
        const float sth2 = STH2[thi];
        const float ASTEP = 3.1f / 7.0f;
        const float rsa0  = ASTEP * (float)rsi;
        const float rsa1  = ASTEP * (float)(rsi + 4);
        const float NITA  = -3.0f / (ASTEP * ASTEP);
        const float4* pb = pairbuf[w];

        #pragma unroll
        for (int s = 0; s < 5; s++) {
            const int tt = tj + s;
            if (tt <= 4) {
                const int beg = off[tt];
                const int cnt = __popc(am[tt]);
                #pragma unroll 4
                for (int q = 0; q < cnt; q++) {
                    const float4 pv = pb[beg + q];   // broadcast LDS.128

                    // ((1 + cos(theta - th_l))/2)^64 via identity + 6 squarings
                    float a = fmaf(pv.x, cth2, fmaf(pv.y, sth2, 0.5f));
                    a = a * a; a = a * a; a = a * a;
                    a = a * a; a = a * a; a = a * a;

                    float d0 = pv.z - rsa0;
                    float d1 = pv.z - rsa1;
                    float g0 = __expf(NITA * d0 * d0);
                    float g1 = __expf(NITA * d1 * d1);

                    float sv = a * pv.w;
                    acc[2 * s]     = fmaf(sv, g0, acc[2 * s]);
                    acc[2 * s + 1] = fmaf(sv, g1, acc[2 * s + 1]);
                }
            }
        }
    }

    // store per-warp partials (zeros for inactive warps)
    #pragma unroll
    for (int s = 0; s < 5; s++) {
        wacc[w][s * 64 + lane]      = acc[2 * s];
        wacc[w][s * 64 + 32 + lane] = acc[2 * s + 1];
    }
    __syncthreads();

    // ---- epilogue: reduce partials, write output ----
    const size_t base = (size_t)(b * NQ + i) * FEAT;
    if (tid == 0) out[base] = (float)anum[b * NQ + i];

    // radial: 160 outputs
    if (tid < 5 * RLQ) {
        const int tt = tid >> 5, c = tid & 31;
        unsigned m = s_rmask[tt];
        float s = 0.0f;
        while (m) { const int a = __ffs(m) - 1; m &= m - 1; s += radp[a][c]; }
        out[base + 1 + tid] = s;
    }

    // angular: 960 outputs
    for (int f = tid; f < NPAIR * 64; f += NT) {
        const int p = f >> 6, c = f & 63;
        const int ta = PA[p], tb = PB[p];
        const int slot = (tb - ta) * 64 + c;
        unsigned m = s_amask[ta];
        float s = 0.0f;
        while (m) { const int a = __ffs(m) - 1; m &= m - 1; s += wacc[a][slot]; }
        out[base + 1 + 5 * RLQ + f] = s;
    }
}

extern "C" void kernel_launch(void* const* d_in, const int* in_sizes, int n_in,
                              void* d_out, int out_size)
{
    const float* coords = (const float*)d_in[0];
    const int*   anum   = (const int*)d_in[1];
    float*       out    = (float*)d_out;
    ani_kernel<<<BQ * NQ, NT>>>(coords, anum, out);
}

// round 11
// speedup vs baseline: 1.0037x; 1.0037x over previous
#include <cuda_runtime.h>
#include <math.h>

// Problem constants
#define BQ 4
#define NQ 23
#define NPAIR 15
#define RLQ 32
#define FEAT 1121          // 1 + 5*32 + 15*64
#define NW 23              // one warp per j-atom
#define NT (NW * 32)       // 736 threads
#define ROWF 320           // floats per warp row in union buffer

// 0.5*cos(theta_l), 0.5*sin(theta_l), theta_l = pi*l/7
__constant__ float CTH2[8] = {
     0.5f,            0.45048443395f,  0.31174490093f,  0.11126046698f,
    -0.11126046698f, -0.31174490093f, -0.45048443395f, -0.5f };
__constant__ float STH2[8] = {
     0.0f,            0.21694186956f,  0.39091574124f,  0.48746395609f,
     0.48746395609f,  0.39091574124f,  0.21694186956f,  0.0f };
// pair p -> (ta, tb), ta<=tb
__constant__ int PA[NPAIR] = {0,0,0,0,0,1,1,1,1,2,2,2,3,3,4};
__constant__ int PB[NPAIR] = {0,1,2,3,4,1,2,3,4,2,3,4,3,4,4};

__global__ __launch_bounds__(NT, 1)
void ani_kernel(const float* __restrict__ coords,
                const int*   __restrict__ anum,
                float*       __restrict__ out)
{
    // Union buffer, one 320-float row per warp:
    //   phase A/B: pair records, 12 floats each: [ct,st,fp,pad, g0..g7]
    //   epilogue : angular partials, 5*64 floats
    // Lifetimes disjoint per row (warp w reads only row w, then overwrites it).
    __shared__ float    uni[NW][ROWF];           // 29440 B
    __shared__ float    radp[NW][RLQ];           // 2944 B
    __shared__ float4   rel[NQ];                 // (dx,dy,dz,dr) wrt atom i
    __shared__ float4   crel[NQ];                // type-compacted rel
    __shared__ float    cfac[NQ];                // type-compacted fac
    __shared__ float    facs[NQ], frcs[NQ];
    __shared__ int      typs[NQ];
    __shared__ unsigned s_amask[5], s_rmask[5];
    __shared__ int      s_off[5], s_cnt[5], s_S;

    const int bi = blockIdx.x;
    const int b  = bi / NQ;
    const int i  = bi % NQ;
    const int tid  = threadIdx.x;
    const int w    = tid >> 5;
    const int lane = tid & 31;
    const unsigned FULL = 0xFFFFFFFFu;

    // ---- warp 0: shared prologue (loads, cutoffs, masks, compaction) ----
    if (w == 0) {
        const bool v = lane < NQ;
        float x = 0.f, y = 0.f, z = 0.f;
        int   t = -1;
        if (v) {
            const float BOHR = 0.52917721092f;
            x = coords[(b * NQ + lane) * 3 + 0] * BOHR;
            y = coords[(b * NQ + lane) * 3 + 1] * BOHR;
            z = coords[(b * NQ + lane) * 3 + 2] * BOHR;
            int zz = anum[b * NQ + lane];
            t = (zz == 1) ? 0 : (zz == 6) ? 1 : (zz == 7) ? 2 :
                (zz == 8) ? 3 : (zz == 16) ? 4 : -1;
        }
        const float xi = __shfl_sync(FULL, x, i);
        const float yi = __shfl_sync(FULL, y, i);
        const float zi = __shfl_sync(FULL, z, i);

        const float dx = x - xi, dy = y - yi, dz = z - zi;
        const float dr = sqrtf(dx * dx + dy * dy + dz * dz + 1e-7f);
        const bool  ne = v && (lane != i);
        const float fr = (ne && dr < 4.6f) ? 0.5f * (__cosf(0.68294733639181f * dr) + 1.0f) : 0.0f;
        const float fa = (ne && dr < 3.1f) ? 0.5f * (__cosf(1.01341709287626f * dr) + 1.0f) : 0.0f;

        unsigned am[5];
        int offv = 0;
        #pragma unroll
        for (int tt = 0; tt < 5; tt++) {
            am[tt] = __ballot_sync(FULL, (t == tt) && (fa > 0.0f));
            unsigned rmv = __ballot_sync(FULL, (t == tt));
            if (lane == 0) {
                s_amask[tt] = am[tt];
                s_rmask[tt] = rmv;
                s_off[tt]   = offv;
                s_cnt[tt]   = __popc(am[tt]);
            }
            offv += __popc(am[tt]);
        }
        if (lane == 0) s_S = offv;

        if (v) {
            rel[lane]  = make_float4(dx, dy, dz, dr);
            facs[lane] = fa;
            frcs[lane] = fr;
            typs[lane] = t;
        }
        // compaction by type
        if (t >= 0 && fa > 0.0f) {
            int base = 0;
            #pragma unroll
            for (int tt = 0; tt < 5; tt++) if (tt < t) base += __popc(am[tt]);
            int slot = base + __popc(am[t] & ((1u << lane) - 1u));
            crel[slot] = make_float4(dx, dy, dz, dr);
            cfac[slot] = fa;
        }
    }
    __syncthreads();

    // per-warp j values (broadcast LDS)
    const int    tj  = typs[w];
    const float  fj  = facs[w];
    const float  fjr = frcs[w];
    const float4 rj  = rel[w];
    const bool   act = (tj >= 0) && (fj > 0.0f);

    // ---- radial partial: warp w, one shell per lane ----
    {
        const float step = 4.6f / 31.0f;
        const float nita = -3.0f / (step * step);
        float rv = 0.0f;
        if (tj >= 0 && fjr > 0.0f) {
            float dd = rj.w - step * (float)lane;
            rv = __expf(nita * dd * dd) * fjr;
        }
        radp[w][lane] = rv;
    }

    float* row = uni[w];

    // ---- phase A: lane = compacted pair slot; ALL exponentials here ----
    const int S = s_S;
    if (act && lane < S) {
        const float4 rk = crel[lane];
        const float  fk = cfac[lane];

        float vm = rj.x * rk.x + rj.y * rk.y + rj.z * rk.z;
        float ct = __fdividef(vm, fmaf(rj.w, rk.w, 1e-5f));
        float x2 = fmaxf(1.0f - ct * ct, 0.0f);
        float st = x2 * rsqrtf(fmaxf(x2, 1e-12f));   // sin(arccos(ct))
        float rv = fmaf(rk.w, 0.5f, 0.5f * rj.w);    // (d_j + d_k)/2
        float fp = 2.0f * fj * fk;

        float* rec = row + lane * 12;
        *(float4*)rec = make_float4(ct, st, fp, 0.0f);   // 48B-aligned

        const float ASTEP = 3.1f / 7.0f;
        const float NITA  = -3.0f / (ASTEP * ASTEP);
        #pragma unroll
        for (int r = 0; r < 8; r++) {
            float dd = rv - ASTEP * (float)r;
            rec[4 + r] = __expf(NITA * dd * dd);
        }
    }
    __syncwarp();

    // ---- phase B: dense counted loops, MUFU-free inner body ----
    float acc[10] = {0.f,0.f,0.f,0.f,0.f,0.f,0.f,0.f,0.f,0.f};
    if (act) {
        const int   thi  = lane & 7;
        const int   rsi  = lane >> 3;
        const float cth2 = CTH2[thi];
        const float sth2 = STH2[thi];

        #pragma unroll
        for (int s = 0; s < 5; s++) {
            const int tt = tj + s;
            if (tt <= 4) {
                const int beg = s_off[tt];
                const int cnt = s_cnt[tt];
                #pragma unroll 4
                for (int q = 0; q < cnt; q++) {
                    const float* rec = row + (beg + q) * 12;  // warp-uniform
                    const float4 pv = *(const float4*)rec;    // broadcast LDS.128

                    // ((1 + cos(theta - th_l))/2)^64: identity + 6 squarings
                    float a = fmaf(pv.x, cth2, fmaf(pv.y, sth2, 0.5f));
                    a = a * a; a = a * a; a = a * a;
                    a = a * a; a = a * a; a = a * a;

                    float g0 = rec[4 + rsi];       // broadcast LDS.32
                    float g1 = rec[8 + rsi];

                    float sv = a * pv.z;
                    acc[2 * s]     = fmaf(sv, g0, acc[2 * s]);
                    acc[2 * s + 1] = fmaf(sv, g1, acc[2 * s + 1]);
                }
            }
        }
    }
    __syncwarp();   // all lanes of this warp done reading row before overwrite

    // overwrite own row with angular partials (zeros for inactive warps)
    #pragma unroll
    for (int s = 0; s < 5; s++) {
        row[s * 64 + lane]      = acc[2 * s];
        row[s * 64 + 32 + lane] = acc[2 * s + 1];
    }
    __syncthreads();

    // ---- epilogue: reduce partials, write output ----
    const size_t base = (size_t)(b * NQ + i) * FEAT;
    if (tid == 0) out[base] = (float)anum[b * NQ + i];

    // radial: 160 outputs
    if (tid < 5 * RLQ) {
        const int tt = tid >> 5, c = tid & 31;
        unsigned m = s_rmask[tt];
        float s = 0.0f;
        while (m) { const int a = __ffs(m) - 1; m &= m - 1; s += radp[a][c]; }
        out[base + 1 + tid] = s;
    }

    // angular: 960 outputs
    for (int f = tid; f < NPAIR * 64; f += NT) {
        const int p = f >> 6, c = f & 63;
        const int ta = PA[p], tb = PB[p];
        const int slot = (tb - ta) * 64 + c;
        unsigned m = s_amask[ta];
        float s = 0.0f;
        while (m) { const int a = __ffs(m) - 1; m &= m - 1; s += uni[a][slot]; }
        out[base + 1 + 5 * RLQ + f] = s;
    }
}

extern "C" void kernel_launch(void* const* d_in, const int* in_sizes, int n_in,
                              void* d_out, int out_size)
{
    const float* coords = (const float*)d_in[0];
    const int*   anum   = (const int*)d_in[1];
    float*       out    = (float*)d_out;
    ani_kernel<<<BQ * NQ, NT>>>(coords, anum, out);
}

// round 13
// speedup vs baseline: 1.0543x; 1.0504x over previous
#include <cuda_runtime.h>
#include <math.h>

// Problem constants
#define BQ 4
#define NQ 23
#define NPAIR 15
#define RLQ 32
#define FEAT 1121          // 1 + 5*32 + 15*64
#define NW 23              // one warp per j-atom
#define NT (NW * 32)       // 736 threads
#define ROWF 320           // floats per warp row in union buffer

// 0.5*cos(theta_l), 0.5*sin(theta_l), theta_l = pi*l/7
__constant__ float CTH2[8] = {
     0.5f,            0.45048443395f,  0.31174490093f,  0.11126046698f,
    -0.11126046698f, -0.31174490093f, -0.45048443395f, -0.5f };
__constant__ float STH2[8] = {
     0.0f,            0.21694186956f,  0.39091574124f,  0.48746395609f,
     0.48746395609f,  0.39091574124f,  0.21694186956f,  0.0f };
// pair p -> (ta, tb), ta<=tb
__constant__ int PA[NPAIR] = {0,0,0,0,0,1,1,1,1,2,2,2,3,3,4};
__constant__ int PB[NPAIR] = {0,1,2,3,4,1,2,3,4,2,3,4,3,4,4};

__global__ __launch_bounds__(NT, 1)
void ani_kernel(const float* __restrict__ coords,
                const int*   __restrict__ anum,
                float*       __restrict__ out)
{
    // Union buffer, one 320-float row per warp:
    //   phase A/B: pair records, 12 floats each: [ct,st,fp,pad, g0..g7]
    //   epilogue : angular partials, 5*64 floats
    __shared__ float    uni[NW][ROWF];           // 29440 B
    __shared__ float4   rel[NQ];                 // (dx,dy,dz,dr) wrt atom i
    __shared__ float4   crel[NQ];                // type-compacted rel
    __shared__ float    cfac[NQ];                // type-compacted fac
    __shared__ float    facs[NQ], frcs[NQ];
    __shared__ int      typs[NQ];
    __shared__ unsigned s_amask[5], s_rmask[5];
    __shared__ int      s_off[5], s_cnt[5], s_S;

    const int bi = blockIdx.x;
    const int b  = bi / NQ;
    const int i  = bi % NQ;
    const int tid  = threadIdx.x;
    const int w    = tid >> 5;
    const int lane = tid & 31;
    const unsigned FULL = 0xFFFFFFFFu;

    const size_t obase = (size_t)(b * NQ + i) * FEAT;

    // ---- warp 0: shared prologue (loads, cutoffs, masks, compaction) ----
    if (w == 0) {
        const bool v = lane < NQ;
        float x = 0.f, y = 0.f, z = 0.f;
        int   t = -1, zz = 0;
        if (v) {
            const float BOHR = 0.52917721092f;
            x = coords[(b * NQ + lane) * 3 + 0] * BOHR;
            y = coords[(b * NQ + lane) * 3 + 1] * BOHR;
            z = coords[(b * NQ + lane) * 3 + 2] * BOHR;
            zz = anum[b * NQ + lane];
            t = (zz == 1) ? 0 : (zz == 6) ? 1 : (zz == 7) ? 2 :
                (zz == 8) ? 3 : (zz == 16) ? 4 : -1;
        }
        if (lane == i) out[obase] = (float)zz;   // early scalar write

        const float xi = __shfl_sync(FULL, x, i);
        const float yi = __shfl_sync(FULL, y, i);
        const float zi = __shfl_sync(FULL, z, i);

        const float dx = x - xi, dy = y - yi, dz = z - zi;
        const float dr = sqrtf(dx * dx + dy * dy + dz * dz + 1e-7f);
        const bool  ne = v && (lane != i);
        const float fr = (ne && dr < 4.6f) ? 0.5f * (__cosf(0.68294733639181f * dr) + 1.0f) : 0.0f;
        const float fa = (ne && dr < 3.1f) ? 0.5f * (__cosf(1.01341709287626f * dr) + 1.0f) : 0.0f;

        unsigned am[5];
        int offv = 0;
        #pragma unroll
        for (int tt = 0; tt < 5; tt++) {
            am[tt] = __ballot_sync(FULL, (t == tt) && (fa > 0.0f));
            unsigned rmv = __ballot_sync(FULL, (t == tt));
            if (lane == 0) {
                s_amask[tt] = am[tt];
                s_rmask[tt] = rmv;
                s_off[tt]   = offv;
                s_cnt[tt]   = __popc(am[tt]);
            }
            offv += __popc(am[tt]);
        }
        if (lane == 0) s_S = offv;

        if (v) {
            rel[lane]  = make_float4(dx, dy, dz, dr);
            facs[lane] = fa;
            frcs[lane] = fr;
            typs[lane] = t;
        }
        // compaction by type
        if (t >= 0 && fa > 0.0f) {
            int base = 0;
            #pragma unroll
            for (int tt = 0; tt < 5; tt++) if (tt < t) base += __popc(am[tt]);
            int slot = base + __popc(am[t] & ((1u << lane) - 1u));
            crel[slot] = make_float4(dx, dy, dz, dr);
            cfac[slot] = fa;
        }
    }
    __syncthreads();

    // ---- radial: warps 0-4, one type each, direct STG (off epilogue path) ----
    if (w < 5) {
        const float step = 4.6f / 31.0f;
        const float nita = -3.0f / (step * step);
        const float rs   = step * (float)lane;
        unsigned m = s_rmask[w];
        float s = 0.0f;
        while (m) {
            const int j = __ffs(m) - 1; m &= m - 1;
            const float fr = frcs[j];
            if (fr > 0.0f) {
                float dd = rel[j].w - rs;
                s = fmaf(__expf(nita * dd * dd), fr, s);
            }
        }
        out[obase + 1 + w * RLQ + lane] = s;
    }

    // per-warp j values (broadcast LDS)
    const int    tj  = typs[w];
    const float  fj  = facs[w];
    const float4 rj  = rel[w];
    const bool   act = (tj >= 0) && (fj > 0.0f);

    float* row = uni[w];

    // ---- phase A: lane = compacted pair slot; ALL exponentials here ----
    const int S = s_S;
    if (act && lane < S) {
        const float4 rk = crel[lane];
        const float  fk = cfac[lane];

        float vm = rj.x * rk.x + rj.y * rk.y + rj.z * rk.z;
        float ct = __fdividef(vm, fmaf(rj.w, rk.w, 1e-5f));
        float x2 = fmaxf(1.0f - ct * ct, 0.0f);
        float st = x2 * rsqrtf(fmaxf(x2, 1e-12f));   // sin(arccos(ct))
        float rv = fmaf(rk.w, 0.5f, 0.5f * rj.w);    // (d_j + d_k)/2
        float fp = 2.0f * fj * fk;

        float* rec = row + lane * 12;
        *(float4*)rec = make_float4(ct, st, fp, 0.0f);

        const float ASTEP = 3.1f / 7.0f;
        const float NITA  = -3.0f / (ASTEP * ASTEP);
        #pragma unroll
        for (int r = 0; r < 8; r++) {
            float dd = rv - ASTEP * (float)r;
            rec[4 + r] = __expf(NITA * dd * dd);
        }
    }
    __syncwarp();

    // ---- phase B: dense counted loops, MUFU-free inner body ----
    if (act) {
        float acc[10] = {0.f,0.f,0.f,0.f,0.f,0.f,0.f,0.f,0.f,0.f};
        const int   thi  = lane & 7;
        const int   rsi  = lane >> 3;
        const float cth2 = CTH2[thi];
        const float sth2 = STH2[thi];

        #pragma unroll
        for (int s = 0; s < 5; s++) {
            const int tt = tj + s;
            if (tt <= 4) {
                const int beg = s_off[tt];
                const int cnt = s_cnt[tt];
                #pragma unroll 4
                for (int q = 0; q < cnt; q++) {
                    const float* rec = row + (beg + q) * 12;  // warp-uniform
                    const float4 pv = *(const float4*)rec;    // broadcast LDS.128

                    // ((1 + cos(theta - th_l))/2)^64: identity + 6 squarings
                    float a = fmaf(pv.x, cth2, fmaf(pv.y, sth2, 0.5f));
                    a = a * a; a = a * a; a = a * a;
                    a = a * a; a = a * a; a = a * a;

                    float g0 = rec[4 + rsi];       // broadcast LDS.32
                    float g1 = rec[8 + rsi];

                    float sv = a * pv.z;
                    acc[2 * s]     = fmaf(sv, g0, acc[2 * s]);
                    acc[2 * s + 1] = fmaf(sv, g1, acc[2 * s + 1]);
                }
            }
        }
        __syncwarp();   // row reads done before overwrite
        #pragma unroll
        for (int s = 0; s < 5; s++) {
            row[s * 64 + lane]      = acc[2 * s];
            row[s * 64 + 32 + lane] = acc[2 * s + 1];
        }
    }
    __syncthreads();

    // ---- epilogue: angular reduction over ACTIVE rows only ----
    for (int f = tid; f < NPAIR * 64; f += NT) {
        const int p = f >> 6, c = f & 63;
        const int ta = PA[p], tb = PB[p];
        const int slot = (tb - ta) * 64 + c;
        unsigned m = s_amask[ta];
        float s = 0.0f;
        while (m) { const int a = __ffs(m) - 1; m &= m - 1; s += uni[a][slot]; }
        out[obase + 1 + 5 * RLQ + f] = s;
    }
}

extern "C" void kernel_launch(void* const* d_in, const int* in_sizes, int n_in,
                              void* d_out, int out_size)
{
    const float* coords = (const float*)d_in[0];
    const int*   anum   = (const int*)d_in[1];
    float*       out    = (float*)d_out;
    ani_kernel<<<BQ * NQ, NT>>>(coords, anum, out);
}

// round 14
// speedup vs baseline: 1.2891x; 1.2227x over previous
#include <cuda_runtime.h>
#include <math.h>

// Problem constants
#define BQ 4
#define NQ 23
#define NPAIR 15
#define RLQ 32
#define FEAT 1121          // 1 + 5*32 + 15*64
#define NW 23              // one warp per j-atom
#define NT (NW * 32)       // 736 threads
#define ROWF 320           // floats per warp row in union buffer

// 0.5*cos(theta_l), 0.5*sin(theta_l), theta_l = pi*l/7
__constant__ float CTH2[8] = {
     0.5f,            0.45048443395f,  0.31174490093f,  0.11126046698f,
    -0.11126046698f, -0.31174490093f, -0.45048443395f, -0.5f };
__constant__ float STH2[8] = {
     0.0f,            0.21694186956f,  0.39091574124f,  0.48746395609f,
     0.48746395609f,  0.39091574124f,  0.21694186956f,  0.0f };
// pair p -> (ta, tb), ta<=tb
__constant__ int PA[NPAIR] = {0,0,0,0,0,1,1,1,1,2,2,2,3,3,4};
__constant__ int PB[NPAIR] = {0,1,2,3,4,1,2,3,4,2,3,4,3,4,4};

__global__ __launch_bounds__(NT, 1)
void ani_kernel(const float* __restrict__ coords,
                const int*   __restrict__ anum,
                float*       __restrict__ out)
{
    // Union buffer, one 320-float row per warp:
    //   phase A/B: pair records, 12 floats each: [ct,st,fp,pad, g0..g7]
    //   epilogue : angular partials, 5*64 floats
    __shared__ float    uni[NW][ROWF];           // 29440 B
    __shared__ float4   rel[NQ];                 // (dx,dy,dz,dr) wrt atom i
    __shared__ float4   crel[NQ];                // type-compacted rel
    __shared__ float    cfac[NQ];                // type-compacted fac
    __shared__ float    facs[NQ], frcs[NQ];
    __shared__ int      typs[NQ];
    __shared__ unsigned s_amask[5], s_rmask[5];
    __shared__ int      s_off[5], s_cnt[5], s_S;

    const int bi = blockIdx.x;
    const int b  = bi / NQ;
    const int i  = bi % NQ;
    const int tid  = threadIdx.x;
    const int w    = tid >> 5;
    const int lane = tid & 31;
    const unsigned FULL = 0xFFFFFFFFu;

    const size_t obase = (size_t)(b * NQ + i) * FEAT;

    // ---- warp 0: shared prologue (loads, cutoffs, masks, compaction) ----
    if (w == 0) {
        const bool v = lane < NQ;
        float x = 0.f, y = 0.f, z = 0.f;
        int   t = -1, zz = 0;
        if (v) {
            const float BOHR = 0.52917721092f;
            x = coords[(b * NQ + lane) * 3 + 0] * BOHR;
            y = coords[(b * NQ + lane) * 3 + 1] * BOHR;
            z = coords[(b * NQ + lane) * 3 + 2] * BOHR;
            zz = anum[b * NQ + lane];
            t = (zz == 1) ? 0 : (zz == 6) ? 1 : (zz == 7) ? 2 :
                (zz == 8) ? 3 : (zz == 16) ? 4 : -1;
        }
        if (lane == i) out[obase] = (float)zz;   // early scalar write

        const float xi = __shfl_sync(FULL, x, i);
        const float yi = __shfl_sync(FULL, y, i);
        const float zi = __shfl_sync(FULL, z, i);

        const float dx = x - xi, dy = y - yi, dz = z - zi;
        const float dr = sqrtf(dx * dx + dy * dy + dz * dz + 1e-7f);
        const bool  ne = v && (lane != i);
        const float fr = (ne && dr < 4.6f) ? 0.5f * (__cosf(0.68294733639181f * dr) + 1.0f) : 0.0f;
        const float fa = (ne && dr < 3.1f) ? 0.5f * (__cosf(1.01341709287626f * dr) + 1.0f) : 0.0f;

        unsigned am[5];
        int offv = 0;
        #pragma unroll
        for (int tt = 0; tt < 5; tt++) {
            am[tt] = __ballot_sync(FULL, (t == tt) && (fa > 0.0f));
            unsigned rmv = __ballot_sync(FULL, (t == tt));
            if (lane == 0) {
                s_amask[tt] = am[tt];
                s_rmask[tt] = rmv;
                s_off[tt]   = offv;
                s_cnt[tt]   = __popc(am[tt]);
            }
            offv += __popc(am[tt]);
        }
        if (lane == 0) s_S = offv;

        if (v) {
            rel[lane]  = make_float4(dx, dy, dz, dr);
            facs[lane] = fa;
            frcs[lane] = fr;
            typs[lane] = t;
        }
        // compaction by type
        if (t >= 0 && fa > 0.0f) {
            int base = 0;
            #pragma unroll
            for (int tt = 0; tt < 5; tt++) if (tt < t) base += __popc(am[tt]);
            int slot = base + __popc(am[t] & ((1u << lane) - 1u));
            crel[slot] = make_float4(dx, dy, dz, dr);
            cfac[slot] = fa;
        }
    }
    __syncthreads();

    // ---- radial: warps 0-4, one type each, direct STG (off epilogue path) ----
    if (w < 5) {
        const float step = 4.6f / 31.0f;
        const float nita = -3.0f / (step * step);
        const float rs   = step * (float)lane;
        unsigned m = s_rmask[w];
        float s = 0.0f;
        while (m) {
            const int j = __ffs(m) - 1; m &= m - 1;
            const float fr = frcs[j];
            if (fr > 0.0f) {
                float dd = rel[j].w - rs;
                s = fmaf(__expf(nita * dd * dd), fr, s);
            }
        }
        out[obase + 1 + w * RLQ + lane] = s;
    }

    // per-warp j values (broadcast LDS)
    const int    tj  = typs[w];
    const float  fj  = facs[w];
    const float4 rj  = rel[w];
    const bool   act = (tj >= 0) && (fj > 0.0f);

    float* row = uni[w];

    // ---- phase A: lane = compacted pair slot; ALL exponentials here ----
    const int S = s_S;
    if (act && lane < S) {
        const float4 rk = crel[lane];
        const float  fk = cfac[lane];

        float vm = rj.x * rk.x + rj.y * rk.y + rj.z * rk.z;
        float ct = __fdividef(vm, fmaf(rj.w, rk.w, 1e-5f));
        float x2 = fmaxf(1.0f - ct * ct, 0.0f);
        float st = x2 * rsqrtf(fmaxf(x2, 1e-12f));   // sin(arccos(ct))
        float rv = fmaf(rk.w, 0.5f, 0.5f * rj.w);    // (d_j + d_k)/2
        float fp = 2.0f * fj * fk;

        float* rec = row + lane * 12;
        *(float4*)rec = make_float4(ct, st, fp, 0.0f);

        const float ASTEP = 3.1f / 7.0f;
        const float NITA  = -3.0f / (ASTEP * ASTEP);
        #pragma unroll
        for (int r = 0; r < 8; r++) {
            float dd = rv - ASTEP * (float)r;
            rec[4 + r] = __expf(NITA * dd * dd);
        }
    }
    __syncwarp();

    // ---- phase B: dense counted loops, MUFU-free inner body ----
    if (act) {
        float acc[10] = {0.f,0.f,0.f,0.f,0.f,0.f,0.f,0.f,0.f,0.f};
        const int   thi  = lane & 7;
        const int   rsi  = lane >> 3;
        const float cth2 = CTH2[thi];
        const float sth2 = STH2[thi];

        #pragma unroll
        for (int s = 0; s < 5; s++) {
            const int tt = tj + s;
            if (tt <= 4) {
                const int beg = s_off[tt];
                const int cnt = s_cnt[tt];
                #pragma unroll 4
                for (int q = 0; q < cnt; q++) {
                    const float* rec = row + (beg + q) * 12;  // warp-uniform
                    const float4 pv = *(const float4*)rec;    // broadcast LDS.128

                    // ((1 + cos(theta - th_l))/2)^64: identity + 6 squarings
                    float a = fmaf(pv.x, cth2, fmaf(pv.y, sth2, 0.5f));
                    a = a * a; a = a * a; a = a * a;
                    a = a * a; a = a * a; a = a * a;

                    float g0 = rec[4 + rsi];       // broadcast LDS.32
                    float g1 = rec[8 + rsi];

                    float sv = a * pv.z;
                    acc[2 * s]     = fmaf(sv, g0, acc[2 * s]);
                    acc[2 * s + 1] = fmaf(sv, g1, acc[2 * s + 1]);
                }
            }
        }
        __syncwarp();   // row reads done before overwrite
        #pragma unroll
        for (int s = 0; s < 5; s++) {
            row[s * 64 + lane]      = acc[2 * s];
            row[s * 64 + 32 + lane] = acc[2 * s + 1];
        }
    }
    __syncthreads();

    // ---- epilogue: angular reduction over ACTIVE rows only ----
    for (int f = tid; f < NPAIR * 64; f += NT) {
        const int p = f >> 6, c = f & 63;
        const int ta = PA[p], tb = PB[p];
        const int slot = (tb - ta) * 64 + c;
        unsigned m = s_amask[ta];
        float s = 0.0f;
        while (m) { const int a = __ffs(m) - 1; m &= m - 1; s += uni[a][slot]; }
        out[obase + 1 + 5 * RLQ + f] = s;
    }
}

extern "C" void kernel_launch(void* const* d_in, const int* in_sizes, int n_in,
                              void* d_out, int out_size)
{
    const float* coords = (const float*)d_in[0];
    const int*   anum   = (const int*)d_in[1];
    float*       out    = (float*)d_out;
    ani_kernel<<<BQ * NQ, NT>>>(coords, anum, out);
}

// round 15
// speedup vs baseline: 1.3077x; 1.0144x over previous
#include <cuda_runtime.h>
#include <math.h>

// Problem constants
#define BQ 4
#define NQ 23
#define NPAIR 15
#define RLQ 32
#define FEAT 1121          // 1 + 5*32 + 15*64
#define NW 23              // one warp per j-atom
#define NT (NW * 32)       // 736 threads
#define ROWF 320           // floats per warp row in union buffer

// 0.5*cos(theta_l), 0.5*sin(theta_l), theta_l = pi*l/7
__constant__ float CTH2[8] = {
     0.5f,            0.45048443395f,  0.31174490093f,  0.11126046698f,
    -0.11126046698f, -0.31174490093f, -0.45048443395f, -0.5f };
__constant__ float STH2[8] = {
     0.0f,            0.21694186956f,  0.39091574124f,  0.48746395609f,
     0.48746395609f,  0.39091574124f,  0.21694186956f,  0.0f };
// pair p -> (ta, tb), ta<=tb
__constant__ int PA[NPAIR] = {0,0,0,0,0,1,1,1,1,2,2,2,3,3,4};
__constant__ int PB[NPAIR] = {0,1,2,3,4,1,2,3,4,2,3,4,3,4,4};

__global__ __launch_bounds__(NT, 1)
void ani_kernel(const float* __restrict__ coords,
                const int*   __restrict__ anum,
                float*       __restrict__ out)
{
    // Union buffer, one 320-float row per warp:
    //   phase A/B: pair records, 12 floats each: [ct,st,fp,pad, g0..g7]
    //   epilogue : angular partials, 5*64 floats
    __shared__ float    uni[NW][ROWF];           // 29440 B
    __shared__ float4   rel[NQ];                 // (dx,dy,dz,dr) wrt atom i
    __shared__ float4   crel[NQ];                // type-compacted rel
    __shared__ float    cfac[NQ];                // type-compacted fac
    __shared__ float    facs[NQ], frcs[NQ];
    __shared__ int      typs[NQ];
    __shared__ unsigned s_amask[5], s_rmask[5];
    __shared__ int      s_off[5], s_cnt[5], s_S;

    const int bi = blockIdx.x;
    const int b  = bi / NQ;
    const int i  = bi % NQ;
    const int tid  = threadIdx.x;
    const int w    = tid >> 5;
    const int lane = tid & 31;
    const unsigned FULL = 0xFFFFFFFFu;

    const size_t obase = (size_t)(b * NQ + i) * FEAT;

    // ---- warp 0: shared prologue (loads, cutoffs, masks, compaction) ----
    if (w == 0) {
        const bool v = lane < NQ;
        float x = 0.f, y = 0.f, z = 0.f;
        int   t = -1, zz = 0;
        if (v) {
            const float BOHR = 0.52917721092f;
            x = coords[(b * NQ + lane) * 3 + 0] * BOHR;
            y = coords[(b * NQ + lane) * 3 + 1] * BOHR;
            z = coords[(b * NQ + lane) * 3 + 2] * BOHR;
            zz = anum[b * NQ + lane];
            t = (zz == 1) ? 0 : (zz == 6) ? 1 : (zz == 7) ? 2 :
                (zz == 8) ? 3 : (zz == 16) ? 4 : -1;
        }
        if (lane == i) out[obase] = (float)zz;   // early scalar write

        const float xi = __shfl_sync(FULL, x, i);
        const float yi = __shfl_sync(FULL, y, i);
        const float zi = __shfl_sync(FULL, z, i);

        const float dx = x - xi, dy = y - yi, dz = z - zi;
        const float dr = sqrtf(dx * dx + dy * dy + dz * dz + 1e-7f);
        const bool  ne = v && (lane != i);
        const float fr = (ne && dr < 4.6f) ? 0.5f * (__cosf(0.68294733639181f * dr) + 1.0f) : 0.0f;
        const float fa = (ne && dr < 3.1f) ? 0.5f * (__cosf(1.01341709287626f * dr) + 1.0f) : 0.0f;

        unsigned am[5];
        int offv = 0;
        #pragma unroll
        for (int tt = 0; tt < 5; tt++) {
            am[tt] = __ballot_sync(FULL, (t == tt) && (fa > 0.0f));
            unsigned rmv = __ballot_sync(FULL, (t == tt));
            if (lane == 0) {
                s_amask[tt] = am[tt];
                s_rmask[tt] = rmv;
                s_off[tt]   = offv;
                s_cnt[tt]   = __popc(am[tt]);
            }
            offv += __popc(am[tt]);
        }
        if (lane == 0) s_S = offv;

        if (v) {
            rel[lane]  = make_float4(dx, dy, dz, dr);
            facs[lane] = fa;
            frcs[lane] = fr;
            typs[lane] = t;
        }
        // compaction by type
        if (t >= 0 && fa > 0.0f) {
            int base = 0;
            #pragma unroll
            for (int tt = 0; tt < 5; tt++) if (tt < t) base += __popc(am[tt]);
            int slot = base + __popc(am[t] & ((1u << lane) - 1u));
            crel[slot] = make_float4(dx, dy, dz, dr);
            cfac[slot] = fa;
        }
    }
    __syncthreads();

    // ---- radial: warps 0-4, one type each, direct STG (off epilogue path) ----
    if (w < 5) {
        const float step = 4.6f / 31.0f;
        const float nita = -3.0f / (step * step);
        const float rs   = step * (float)lane;
        unsigned m = s_rmask[w];
        float s = 0.0f;
        while (m) {
            const int j = __ffs(m) - 1; m &= m - 1;
            const float fr = frcs[j];
            if (fr > 0.0f) {
                float dd = rel[j].w - rs;
                s = fmaf(__expf(nita * dd * dd), fr, s);
            }
        }
        out[obase + 1 + w * RLQ + lane] = s;
    }

    // per-warp j values (broadcast LDS)
    const int    tj  = typs[w];
    const float  fj  = facs[w];
    const float4 rj  = rel[w];
    const bool   act = (tj >= 0) && (fj > 0.0f);

    float* row = uni[w];

    // ---- phase A: lane = compacted pair slot; ALL exponentials here ----
    const int S = s_S;
    if (act && lane < S) {
        const float4 rk = crel[lane];
        const float  fk = cfac[lane];

        float vm = rj.x * rk.x + rj.y * rk.y + rj.z * rk.z;
        float ct = __fdividef(vm, fmaf(rj.w, rk.w, 1e-5f));
        float x2 = fmaxf(1.0f - ct * ct, 0.0f);
        float st = x2 * rsqrtf(fmaxf(x2, 1e-12f));   // sin(arccos(ct))
        float rv = fmaf(rk.w, 0.5f, 0.5f * rj.w);    // (d_j + d_k)/2
        float fp = 2.0f * fj * fk;

        float* rec = row + lane * 12;
        *(float4*)rec = make_float4(ct, st, fp, 0.0f);

        const float ASTEP = 3.1f / 7.0f;
        const float NITA  = -3.0f / (ASTEP * ASTEP);
        #pragma unroll
        for (int r = 0; r < 8; r++) {
            float dd = rv - ASTEP * (float)r;
            rec[4 + r] = __expf(NITA * dd * dd);
        }
    }
    __syncwarp();

    // ---- phase B: dense counted loops, MUFU-free inner body ----
    if (act) {
        float acc[10] = {0.f,0.f,0.f,0.f,0.f,0.f,0.f,0.f,0.f,0.f};
        const int   thi  = lane & 7;
        const int   rsi  = lane >> 3;
        const float cth2 = CTH2[thi];
        const float sth2 = STH2[thi];

        #pragma unroll
        for (int s = 0; s < 5; s++) {
            const int tt = tj + s;
            if (tt <= 4) {
                const int beg = s_off[tt];
                const int cnt = s_cnt[tt];
                #pragma unroll 4
                for (int q = 0; q < cnt; q++) {
                    const float* rec = row + (beg + q) * 12;  // warp-uniform
                    const float4 pv = *(const float4*)rec;    // broadcast LDS.128

                    // ((1 + cos(theta - th_l))/2)^64: identity + 6 squarings
                    float a = fmaf(pv.x, cth2, fmaf(pv.y, sth2, 0.5f));
                    a = a * a; a = a * a; a = a * a;
                    a = a * a; a = a * a; a = a * a;

                    float g0 = rec[4 + rsi];       // broadcast LDS.32
                    float g1 = rec[8 + rsi];

                    float sv = a * pv.z;
                    acc[2 * s]     = fmaf(sv, g0, acc[2 * s]);
                    acc[2 * s + 1] = fmaf(sv, g1, acc[2 * s + 1]);
                }
            }
        }
        __syncwarp();   // row reads done before overwrite
        #pragma unroll
        for (int s = 0; s < 5; s++) {
            row[s * 64 + lane]      = acc[2 * s];
            row[s * 64 + 32 + lane] = acc[2 * s + 1];
        }
    }
    __syncthreads();

    // ---- epilogue: angular reduction over ACTIVE rows only ----
    for (int f = tid; f < NPAIR * 64; f += NT) {
        const int p = f >> 6, c = f & 63;
        const int ta = PA[p], tb = PB[p];
        const int slot = (tb - ta) * 64 + c;
        unsigned m = s_amask[ta];
        float s = 0.0f;
        while (m) { const int a = __ffs(m) - 1; m &= m - 1; s += uni[a][slot]; }
        out[obase + 1 + 5 * RLQ + f] = s;
    }
}

extern "C" void kernel_launch(void* const* d_in, const int* in_sizes, int n_in,
                              void* d_out, int out_size)
{
    const float* coords = (const float*)d_in[0];
    const int*   anum   = (const int*)d_in[1];
    float*       out    = (float*)d_out;
    ani_kernel<<<BQ * NQ, NT>>>(coords, anum, out);
}